// round 1
// baseline (speedup 1.0000x reference)
#include <cuda_runtime.h>

#define NAB 256
#define NAGN 16384
#define NTOT 16640
#define DDIM 128
#define GSZ 2048

// ---------------- scratch (device globals; no allocation) ----------------
__device__ float g_x[NTOT * DDIM];     // concat(selected_ab, x_ag) == layer inputs source
__device__ float g_h[NTOT * DDIM];     // h = x @ W (per layer)
__device__ float g_y[NTOT * DDIM];     // layer-1 output
__device__ float g_z[NTOT * DDIM];     // layer-2 output
__device__ float g_als[NTOT];
__device__ float g_ald[NTOT];
__device__ float g_m[NAB];
__device__ float g_inv[NAB];
__device__ float g_wself[NAB];
__device__ float g_sum[2 * DDIM];
__device__ float g_ssq[2 * DDIM];
__device__ float g_scA[2 * DDIM];
__device__ float g_shA[2 * DDIM];

__device__ __forceinline__ float lrelu(float e) { return e > 0.f ? e : 0.2f * e; }

__device__ __forceinline__ void fma4(float4& a, float s, const float4& v) {
    a.x += s * v.x; a.y += s * v.y; a.z += s * v.z; a.w += s * v.w;
}

// ---------------- concat inputs ----------------
__global__ void k_concat(const float4* __restrict__ ab, const float4* __restrict__ ag) {
    float4* x4 = reinterpret_cast<float4*>(g_x);
    int stride = gridDim.x * blockDim.x;
    for (int i = blockIdx.x * blockDim.x + threadIdx.x; i < NTOT * DDIM / 4; i += stride)
        x4[i] = (i < NAB * DDIM / 4) ? ab[i] : ag[i - NAB * DDIM / 4];
}

// ---------------- GEMM: H = X @ W, plus al_src/al_dst row dots ----------------
// grid 260 blocks x 256 thr, 64 rows per block, full W in dynamic smem.
__global__ void k_gemm(const float* __restrict__ X, const float* __restrict__ W,
                       const float* __restrict__ asrc, const float* __restrict__ adst,
                       float* __restrict__ H, float* __restrict__ ALS, float* __restrict__ ALD) {
    extern __shared__ float sm[];
    float* Ws = sm;                 // 128*128
    float* Xs = sm + 16384;         // 64*128
    const int t = threadIdx.x;
    const int row0 = blockIdx.x * 64;

    const float4* W4 = reinterpret_cast<const float4*>(W);
    float4* Ws4 = reinterpret_cast<float4*>(Ws);
#pragma unroll
    for (int i = 0; i < 16; i++) Ws4[t + 256 * i] = W4[t + 256 * i];
    const float4* X4 = reinterpret_cast<const float4*>(X + (size_t)row0 * DDIM);
    float4* Xs4 = reinterpret_cast<float4*>(Xs);
#pragma unroll
    for (int i = 0; i < 8; i++) Xs4[t + 256 * i] = X4[t + 256 * i];
    __syncthreads();

    const int col4 = t & 31;
    const int rg = t >> 5;
    float acc[8][4];
#pragma unroll
    for (int r = 0; r < 8; r++) { acc[r][0] = acc[r][1] = acc[r][2] = acc[r][3] = 0.f; }

    const float* xb = Xs + rg * 8 * DDIM;
#pragma unroll 8
    for (int k = 0; k < DDIM; k++) {
        float4 w = Ws4[k * 32 + col4];
#pragma unroll
        for (int r = 0; r < 8; r++) {
            float xv = xb[r * DDIM + k];
            acc[r][0] += xv * w.x; acc[r][1] += xv * w.y;
            acc[r][2] += xv * w.z; acc[r][3] += xv * w.w;
        }
    }

    float4* H4 = reinterpret_cast<float4*>(H + (size_t)row0 * DDIM);
    float4 as4 = reinterpret_cast<const float4*>(asrc)[col4];
    float4 ad4 = reinterpret_cast<const float4*>(adst)[col4];
#pragma unroll
    for (int r = 0; r < 8; r++) {
        float4 v = make_float4(acc[r][0], acc[r][1], acc[r][2], acc[r][3]);
        H4[(rg * 8 + r) * 32 + col4] = v;
        float ps = v.x * as4.x + v.y * as4.y + v.z * as4.z + v.w * as4.w;
        float pd = v.x * ad4.x + v.y * ad4.y + v.z * ad4.z + v.w * ad4.w;
#pragma unroll
        for (int off = 16; off; off >>= 1) {
            ps += __shfl_xor_sync(0xffffffffu, ps, off);
            pd += __shfl_xor_sync(0xffffffffu, pd, off);
        }
        if (col4 == 0) {
            ALS[row0 + rg * 8 + r] = ps;
            ALD[row0 + rg * 8 + r] = pd;
        }
    }
}

// ---------------- AB-dst softmax stats (max / inv-denominator / self weight) ----------------
// grid 32 x 256; warp per AB dst. Also zeroes AB rows of the aggregation target.
__global__ void k_softmax_ab(const float* __restrict__ als, const float* __restrict__ ald,
                             float* __restrict__ yzero) {
    const int t = threadIdx.x;
    const int w = t >> 5, l = t & 31;
    const int i = blockIdx.x * 8 + w;   // 0..255
    const int b = i >> 5;
    const float* s = als + NAB + b * GSZ;
    const float aldi = ald[i];

    float mx = -1e30f;
    for (int j = l; j < GSZ; j += 32) mx = fmaxf(mx, lrelu(s[j] + aldi));
    float es = lrelu(als[i] + aldi);
#pragma unroll
    for (int off = 16; off; off >>= 1) mx = fmaxf(mx, __shfl_xor_sync(0xffffffffu, mx, off));
    mx = fmaxf(mx, es);

    float sum = 0.f;
    for (int j = l; j < GSZ; j += 32) sum += __expf(lrelu(s[j] + aldi) - mx);
#pragma unroll
    for (int off = 16; off; off >>= 1) sum += __shfl_xor_sync(0xffffffffu, sum, off);
    float wse = __expf(es - mx);
    if (l == 0) {
        g_m[i] = mx;
        g_inv[i] = 1.f / (sum + wse + 1e-16f);
        g_wself[i] = wse;
    }
    for (int idx = blockIdx.x * 256 + t; idx < NAB * DDIM; idx += 32 * 256) yzero[idx] = 0.f;
}

// ---------------- fused aggregation: AB path (blocks 0..127) + AG path (128..639) ----------------
__global__ void k_agg(const float* __restrict__ h, const float* __restrict__ als,
                      const float* __restrict__ ald, const float* __restrict__ bias,
                      float* __restrict__ y, int do_relu) {
    __shared__ float sbig[4096];            // AB: exp-weights [512 src][8 dst] | AG: h_ab tile 32x128
    __shared__ float ssmall[40];
    __shared__ float4 swT[8][32];           // AG: per-warp source weights (4 dsts packed)
    const int t = threadIdx.x;

    if (blockIdx.x < 128) {
        // -------- AB destinations: 8 dsts x 512-source chunk, atomic partial sums --------
        const int blk = blockIdx.x;
        const int b = blk >> 4, grp = (blk >> 2) & 3, q = blk & 3;
        const int agbase = NAB + b * GSZ + q * 512;
        const int d0 = b * 32 + grp * 8;
        float* m_sh = ssmall;
        float* ald_sh = ssmall + 8;
        if (t < 8) { m_sh[t] = g_m[d0 + t]; ald_sh[t] = ald[d0 + t]; }
        __syncthreads();
        for (int idx = t; idx < 4096; idx += 256) {
            int j = idx >> 3, d = idx & 7;
            sbig[idx] = __expf(lrelu(als[agbase + j] + ald_sh[d]) - m_sh[d]);
        }
        __syncthreads();
        const int c = t & 127, half = t >> 7;
        float acc[8] = {0.f, 0.f, 0.f, 0.f, 0.f, 0.f, 0.f, 0.f};
        const float* hb = h + (size_t)agbase * DDIM + c;
        const float4* w4 = reinterpret_cast<const float4*>(sbig);
        for (int j = half; j < 512; j += 2) {
            float hv = hb[(size_t)j * DDIM];
            float4 wa = w4[j * 2], wb = w4[j * 2 + 1];
            acc[0] += wa.x * hv; acc[1] += wa.y * hv; acc[2] += wa.z * hv; acc[3] += wa.w * hv;
            acc[4] += wb.x * hv; acc[5] += wb.y * hv; acc[6] += wb.z * hv; acc[7] += wb.w * hv;
        }
#pragma unroll
        for (int d = 0; d < 8; d++) atomicAdd(&y[(size_t)(d0 + d) * DDIM + c], acc[d]);
    } else {
        // -------- AG destinations: warp handles 4 dsts; 32-row h_ab tile in smem --------
        const int ablk = blockIdx.x - 128;
        const int b = ablk >> 6, chunk = ablk & 63;
        float* als_sh = ssmall;
        {
            const float4* hsrc = reinterpret_cast<const float4*>(h + (size_t)b * 32 * DDIM);
            float4* hd = reinterpret_cast<float4*>(sbig);
#pragma unroll
            for (int i = 0; i < 4; i++) hd[t + 256 * i] = hsrc[t + 256 * i];
            if (t < 32) als_sh[t] = als[b * 32 + t];
        }
        __syncthreads();
        const int w = t >> 5, l = t & 31;
        const int j0 = NAB + b * GSZ + chunk * 32 + w * 4;

        float e[4], es[4], wv[4], inv[4], wself[4];
#pragma unroll
        for (int d = 0; d < 4; d++) {
            float aldv = ald[j0 + d];
            e[d] = lrelu(als_sh[l] + aldv);
            es[d] = lrelu(als[j0 + d] + aldv);
        }
#pragma unroll
        for (int d = 0; d < 4; d++) {
            float m = e[d];
#pragma unroll
            for (int off = 16; off; off >>= 1) m = fmaxf(m, __shfl_xor_sync(0xffffffffu, m, off));
            m = fmaxf(m, es[d]);
            wv[d] = __expf(e[d] - m);
            float s = wv[d];
#pragma unroll
            for (int off = 16; off; off >>= 1) s += __shfl_xor_sync(0xffffffffu, s, off);
            wself[d] = __expf(es[d] - m);
            inv[d] = 1.f / (s + wself[d] + 1e-16f);
        }
        swT[w][l] = make_float4(wv[0], wv[1], wv[2], wv[3]);
        __syncwarp();

        float4 acc[4];
#pragma unroll
        for (int d = 0; d < 4; d++) {
            float4 hs = reinterpret_cast<const float4*>(h + (size_t)(j0 + d) * DDIM)[l];
            acc[d] = make_float4(wself[d] * hs.x, wself[d] * hs.y, wself[d] * hs.z, wself[d] * hs.w);
        }
        const float4* hab4 = reinterpret_cast<const float4*>(sbig);
#pragma unroll 8
        for (int l2 = 0; l2 < 32; l2++) {
            float4 wq = swT[w][l2];
            float4 hv = hab4[l2 * 32 + l];
            fma4(acc[0], wq.x, hv);
            fma4(acc[1], wq.y, hv);
            fma4(acc[2], wq.z, hv);
            fma4(acc[3], wq.w, hv);
        }
        float4 b4 = reinterpret_cast<const float4*>(bias)[l];
#pragma unroll
        for (int d = 0; d < 4; d++) {
            float4 r;
            r.x = acc[d].x * inv[d] + b4.x;
            r.y = acc[d].y * inv[d] + b4.y;
            r.z = acc[d].z * inv[d] + b4.z;
            r.w = acc[d].w * inv[d] + b4.w;
            if (do_relu) {
                r.x = fmaxf(r.x, 0.f); r.y = fmaxf(r.y, 0.f);
                r.z = fmaxf(r.z, 0.f); r.w = fmaxf(r.w, 0.f);
            }
            reinterpret_cast<float4*>(y + (size_t)(j0 + d) * DDIM)[l] = r;
        }
    }
}

// ---------------- finalize AB rows: add self term, normalize, bias (+relu) ----------------
__global__ void k_fin_ab(float* __restrict__ y, const float* __restrict__ h,
                         const float* __restrict__ bias, int do_relu) {
    int idx = blockIdx.x * 256 + threadIdx.x;   // grid 128 => 32768 = NAB*DDIM
    int i = idx >> 7, c = idx & 127;
    float v = (y[idx] + g_wself[i] * h[idx]) * g_inv[i] + bias[c];
    if (do_relu) v = fmaxf(v, 0.f);
    y[idx] = v;
}

// ---------------- BN stats: AB (single block) + zero AG accumulators ----------------
__global__ void k_stats_ab(const float* __restrict__ gab, const float* __restrict__ bab) {
    int c = threadIdx.x;  // 256
    g_sum[c] = 0.f;
    g_ssq[c] = 0.f;
    const float* src = (c < 128) ? (g_z + c) : (g_x + c - 128);
    float s = 0.f, ss = 0.f;
    for (int r = 0; r < NAB; r++) {
        float v = src[(size_t)r * DDIM];
        s += v; ss += v * v;
    }
    float mean = s * (1.f / NAB);
    float var = ss * (1.f / NAB) - mean * mean;
    float sc = gab[c] * rsqrtf(var + 1e-5f);
    g_scA[c] = sc;
    g_shA[c] = bab[c] - mean * sc;
}

// ---------------- BN stats: AG partial sums (atomic) ----------------
__global__ void k_stats_ag() {
    int c = threadIdx.x;
    int r0 = NAB + blockIdx.x * 64;
    const float* src = (c < 128) ? (g_z + (size_t)r0 * DDIM + c)
                                 : (g_x + (size_t)r0 * DDIM + c - 128);
    float s = 0.f, ss = 0.f;
    for (int r = 0; r < 64; r++) {
        float v = src[(size_t)r * DDIM];
        s += v; ss += v * v;
    }
    atomicAdd(&g_sum[c], s);
    atomicAdd(&g_ssq[c], ss);
}

__device__ __forceinline__ void bnss(float s, float q, float g, float b, float invn,
                                     float& sc, float& sh) {
    float mean = s * invn;
    float var = q * invn - mean * mean;
    sc = g * rsqrtf(var + 1e-5f);
    sh = b - mean * sc;
}

// ---------------- fused BN -> ReLU -> FC epilogue, warp per row ----------------
__global__ void k_apply(float* __restrict__ out,
                        const float* __restrict__ fcw, const float* __restrict__ fcb,
                        const float* __restrict__ agw, const float* __restrict__ agb,
                        const float* __restrict__ gag, const float* __restrict__ bag) {
    const int row = blockIdx.x * 8 + (threadIdx.x >> 5);
    const int l = threadIdx.x & 31;
    float4 v1 = reinterpret_cast<const float4*>(g_z + (size_t)row * DDIM)[l];
    float4 v2 = reinterpret_cast<const float4*>(g_x + (size_t)row * DDIM)[l];
    float4 scA, shAv, scB, shB;
    const float* w;
    float fb;
    if (row < NAB) {
        scA = reinterpret_cast<const float4*>(g_scA)[l];
        shAv = reinterpret_cast<const float4*>(g_shA)[l];
        scB = reinterpret_cast<const float4*>(g_scA)[32 + l];
        shB = reinterpret_cast<const float4*>(g_shA)[32 + l];
        w = fcw; fb = fcb[0];
    } else {
        const float invn = 1.f / (float)NAGN;
        float4 s1 = reinterpret_cast<const float4*>(g_sum)[l];
        float4 q1 = reinterpret_cast<const float4*>(g_ssq)[l];
        float4 s2 = reinterpret_cast<const float4*>(g_sum)[32 + l];
        float4 q2 = reinterpret_cast<const float4*>(g_ssq)[32 + l];
        float4 gA = reinterpret_cast<const float4*>(gag)[l];
        float4 bA = reinterpret_cast<const float4*>(bag)[l];
        float4 gB = reinterpret_cast<const float4*>(gag)[32 + l];
        float4 bB = reinterpret_cast<const float4*>(bag)[32 + l];
        bnss(s1.x, q1.x, gA.x, bA.x, invn, scA.x, shAv.x);
        bnss(s1.y, q1.y, gA.y, bA.y, invn, scA.y, shAv.y);
        bnss(s1.z, q1.z, gA.z, bA.z, invn, scA.z, shAv.z);
        bnss(s1.w, q1.w, gA.w, bA.w, invn, scA.w, shAv.w);
        bnss(s2.x, q2.x, gB.x, bB.x, invn, scB.x, shB.x);
        bnss(s2.y, q2.y, gB.y, bB.y, invn, scB.y, shB.y);
        bnss(s2.z, q2.z, gB.z, bB.z, invn, scB.z, shB.z);
        bnss(s2.w, q2.w, gB.w, bB.w, invn, scB.w, shB.w);
        w = agw; fb = agb[0];
    }
    float4 w1 = reinterpret_cast<const float4*>(w)[l];
    float4 w2 = reinterpret_cast<const float4*>(w)[32 + l];
    float sum = 0.f;
    sum += fmaxf(v1.x * scA.x + shAv.x, 0.f) * w1.x;
    sum += fmaxf(v1.y * scA.y + shAv.y, 0.f) * w1.y;
    sum += fmaxf(v1.z * scA.z + shAv.z, 0.f) * w1.z;
    sum += fmaxf(v1.w * scA.w + shAv.w, 0.f) * w1.w;
    sum += fmaxf(v2.x * scB.x + shB.x, 0.f) * w2.x;
    sum += fmaxf(v2.y * scB.y + shB.y, 0.f) * w2.y;
    sum += fmaxf(v2.z * scB.z + shB.z, 0.f) * w2.z;
    sum += fmaxf(v2.w * scB.w + shB.w, 0.f) * w2.w;
#pragma unroll
    for (int off = 16; off; off >>= 1) sum += __shfl_xor_sync(0xffffffffu, sum, off);
    if (l == 0) out[row] = sum + fb;
}

// ---------------- host ----------------
extern "C" void kernel_launch(void* const* d_in, const int* in_sizes, int n_in,
                              void* d_out, int out_size) {
    const float* ab  = (const float*)d_in[0];
    const float* ag  = (const float*)d_in[1];
    const float* W1  = (const float*)d_in[2];
    const float* as1 = (const float*)d_in[3];
    const float* ad1 = (const float*)d_in[4];
    const float* b1  = (const float*)d_in[5];
    const float* W2  = (const float*)d_in[6];
    const float* as2 = (const float*)d_in[7];
    const float* ad2 = (const float*)d_in[8];
    const float* b2  = (const float*)d_in[9];
    const float* gab = (const float*)d_in[10];
    const float* bab = (const float*)d_in[11];
    const float* gag = (const float*)d_in[12];
    const float* bag = (const float*)d_in[13];
    const float* fcw = (const float*)d_in[14];
    const float* fcb = (const float*)d_in[15];
    const float* agw = (const float*)d_in[16];
    const float* agb = (const float*)d_in[17];
    float* out = (float*)d_out;

    float *px, *ph, *py, *pz, *pals, *pald;
    cudaGetSymbolAddress((void**)&px, g_x);
    cudaGetSymbolAddress((void**)&ph, g_h);
    cudaGetSymbolAddress((void**)&py, g_y);
    cudaGetSymbolAddress((void**)&pz, g_z);
    cudaGetSymbolAddress((void**)&pals, g_als);
    cudaGetSymbolAddress((void**)&pald, g_ald);

    const int SMEM_GEMM = (16384 + 8192) * 4;   // 96 KB
    cudaFuncSetAttribute(k_gemm, cudaFuncAttributeMaxDynamicSharedMemorySize, SMEM_GEMM);

    k_concat<<<256, 256>>>((const float4*)ab, (const float4*)ag);

    // ---- layer 1 ----
    k_gemm<<<260, 256, SMEM_GEMM>>>(px, W1, as1, ad1, ph, pals, pald);
    k_softmax_ab<<<32, 256>>>(pals, pald, py);
    k_agg<<<640, 256>>>(ph, pals, pald, b1, py, 1);
    k_fin_ab<<<128, 256>>>(py, ph, b1, 1);

    // ---- layer 2 ----
    k_gemm<<<260, 256, SMEM_GEMM>>>(py, W2, as2, ad2, ph, pals, pald);
    k_softmax_ab<<<32, 256>>>(pals, pald, pz);
    k_agg<<<640, 256>>>(ph, pals, pald, b2, pz, 0);
    k_fin_ab<<<128, 256>>>(pz, ph, b2, 0);

    // ---- BN + FC epilogue ----
    k_stats_ab<<<1, 256>>>(gab, bab);
    k_stats_ag<<<256, 256>>>();
    k_apply<<<2080, 256>>>(out, fcw, fcb, agw, agb, gag, bag);
}

// round 2
// speedup vs baseline: 1.2216x; 1.2216x over previous
#include <cuda_runtime.h>

#define NAB 256
#define NAGN 16384
#define NTOT 16640
#define DDIM 128
#define GSZ 2048

// ---------------- scratch (device globals; no allocation) ----------------
__device__ float g_x[NTOT * DDIM];
__device__ float g_h[NTOT * DDIM];
__device__ float g_y[NTOT * DDIM];
__device__ float g_z[NTOT * DDIM];
__device__ float g_als[NTOT];
__device__ float g_ald[NTOT];
__device__ float g_m[NAB];
__device__ float g_inv[NAB];
__device__ float g_wself[NAB];
__device__ float g_sum[2 * DDIM];
__device__ float g_ssq[2 * DDIM];
__device__ float g_scA[2 * DDIM];
__device__ float g_shA[2 * DDIM];

__device__ __forceinline__ float lrelu(float e) { return e > 0.f ? e : 0.2f * e; }

__device__ __forceinline__ void fma4(float4& a, float s, const float4& v) {
    a.x += s * v.x; a.y += s * v.y; a.z += s * v.z; a.w += s * v.w;
}

// ---------------- concat inputs ----------------
__global__ void k_concat(const float4* __restrict__ ab, const float4* __restrict__ ag) {
    float4* x4 = reinterpret_cast<float4*>(g_x);
    int stride = gridDim.x * blockDim.x;
    for (int i = blockIdx.x * blockDim.x + threadIdx.x; i < NTOT * DDIM / 4; i += stride)
        x4[i] = (i < NAB * DDIM / 4) ? ab[i] : ag[i - NAB * DDIM / 4];
}

// ---------------- GEMM: H = X @ W, plus al_src/al_dst row dots ----------------
// 260 blocks x 256 thr, 64 rows/block. k-chunked x4: 12 LDS.128 per 128 FMA.
__global__ void k_gemm(const float* __restrict__ X, const float* __restrict__ W,
                       const float* __restrict__ asrc, const float* __restrict__ adst,
                       float* __restrict__ H, float* __restrict__ ALS, float* __restrict__ ALD) {
    extern __shared__ float sm[];
    float* Ws = sm;                 // 128*128
    float* Xs = sm + 16384;         // 64*128
    const int t = threadIdx.x;
    const int row0 = blockIdx.x * 64;

    const float4* W4 = reinterpret_cast<const float4*>(W);
    float4* Ws4 = reinterpret_cast<float4*>(Ws);
#pragma unroll
    for (int i = 0; i < 16; i++) Ws4[t + 256 * i] = W4[t + 256 * i];
    const float4* X4 = reinterpret_cast<const float4*>(X + (size_t)row0 * DDIM);
    float4* Xs4 = reinterpret_cast<float4*>(Xs);
#pragma unroll
    for (int i = 0; i < 8; i++) Xs4[t + 256 * i] = X4[t + 256 * i];
    __syncthreads();

    const int col4 = t & 31;
    const int rg = t >> 5;
    float acc[8][4];
#pragma unroll
    for (int r = 0; r < 8; r++) { acc[r][0] = acc[r][1] = acc[r][2] = acc[r][3] = 0.f; }

#pragma unroll 4
    for (int k0 = 0; k0 < DDIM; k0 += 4) {
        float4 w0 = Ws4[(k0 + 0) * 32 + col4];
        float4 w1 = Ws4[(k0 + 1) * 32 + col4];
        float4 w2 = Ws4[(k0 + 2) * 32 + col4];
        float4 w3 = Ws4[(k0 + 3) * 32 + col4];
#pragma unroll
        for (int r = 0; r < 8; r++) {
            float4 xr = Xs4[(rg * 8 + r) * 32 + (k0 >> 2)];
            acc[r][0] += xr.x * w0.x + xr.y * w1.x + xr.z * w2.x + xr.w * w3.x;
            acc[r][1] += xr.x * w0.y + xr.y * w1.y + xr.z * w2.y + xr.w * w3.y;
            acc[r][2] += xr.x * w0.z + xr.y * w1.z + xr.z * w2.z + xr.w * w3.z;
            acc[r][3] += xr.x * w0.w + xr.y * w1.w + xr.z * w2.w + xr.w * w3.w;
        }
    }

    float4* H4 = reinterpret_cast<float4*>(H + (size_t)row0 * DDIM);
    float4 as4 = reinterpret_cast<const float4*>(asrc)[col4];
    float4 ad4 = reinterpret_cast<const float4*>(adst)[col4];
#pragma unroll
    for (int r = 0; r < 8; r++) {
        float4 v = make_float4(acc[r][0], acc[r][1], acc[r][2], acc[r][3]);
        H4[(rg * 8 + r) * 32 + col4] = v;
        float ps = v.x * as4.x + v.y * as4.y + v.z * as4.z + v.w * as4.w;
        float pd = v.x * ad4.x + v.y * ad4.y + v.z * ad4.z + v.w * ad4.w;
#pragma unroll
        for (int off = 16; off; off >>= 1) {
            ps += __shfl_xor_sync(0xffffffffu, ps, off);
            pd += __shfl_xor_sync(0xffffffffu, pd, off);
        }
        if (col4 == 0) {
            ALS[row0 + rg * 8 + r] = ps;
            ALD[row0 + rg * 8 + r] = pd;
        }
    }
}

// ---------------- AB-dst softmax stats: block per dst (256 blocks) ----------------
__global__ void k_softmax_ab(const float* __restrict__ als, const float* __restrict__ ald,
                             float* __restrict__ yzero) {
    __shared__ float red[64];
    const int t = threadIdx.x;
    const int i = blockIdx.x;           // dst 0..255
    const int b = i >> 5;
    const float* s = als + NAB + b * GSZ;
    const float aldi = ald[i];

    float mx = -1e30f;
#pragma unroll
    for (int j = t; j < GSZ; j += 256) mx = fmaxf(mx, lrelu(s[j] + aldi));
#pragma unroll
    for (int off = 16; off; off >>= 1) mx = fmaxf(mx, __shfl_xor_sync(0xffffffffu, mx, off));
    if ((t & 31) == 0) red[t >> 5] = mx;
    __syncthreads();
    if (t < 32) {
        float v = (t < 8) ? red[t] : -1e30f;
#pragma unroll
        for (int off = 4; off; off >>= 1) v = fmaxf(v, __shfl_xor_sync(0xffffffffu, v, off));
        if (t == 0) red[32] = fmaxf(v, lrelu(als[i] + aldi));
    }
    __syncthreads();
    mx = red[32];

    float sum = 0.f;
#pragma unroll
    for (int j = t; j < GSZ; j += 256) sum += __expf(lrelu(s[j] + aldi) - mx);
#pragma unroll
    for (int off = 16; off; off >>= 1) sum += __shfl_xor_sync(0xffffffffu, sum, off);
    if ((t & 31) == 0) red[t >> 5] = sum;
    __syncthreads();
    if (t < 32) {
        float v = (t < 8) ? red[t] : 0.f;
#pragma unroll
        for (int off = 4; off; off >>= 1) v += __shfl_xor_sync(0xffffffffu, v, off);
        if (t == 0) {
            float wse = __expf(lrelu(als[i] + aldi) - mx);
            g_m[i] = mx;
            g_inv[i] = 1.f / (v + wse + 1e-16f);
            g_wself[i] = wse;
        }
    }
    if (t < 128) yzero[i * DDIM + t] = 0.f;
}

// ---------------- fused aggregation: AB (blocks 0..127) + AG (128..639) ----------------
__global__ void k_agg(const float* __restrict__ h, const float* __restrict__ als,
                      const float* __restrict__ ald, const float* __restrict__ bias,
                      float* __restrict__ y, int do_relu) {
    __shared__ float sbig[8192];            // AB: w[512][8] then staging [8rs][8d][128c] | AG: h_ab 32x128
    __shared__ float ssmall[40];
    __shared__ float4 swT[8][32];
    const int t = threadIdx.x;

    if (blockIdx.x < 128) {
        // -------- AB dsts: block = (batch, src-chunk 512, dst-octet) --------
        const int blk = blockIdx.x;
        const int b = blk >> 4, q = (blk >> 2) & 3, dq = blk & 3;
        const int base = NAB + b * GSZ + q * 512;
        const int d0 = b * 32 + dq * 8;
        float* m_sh = ssmall;
        float* ald_sh = ssmall + 8;
        if (t < 8) { m_sh[t] = g_m[d0 + t]; ald_sh[t] = ald[d0 + t]; }
        __syncthreads();
        for (int idx = t; idx < 4096; idx += 256) {
            int j = idx >> 3, d = idx & 7;
            sbig[idx] = __expf(lrelu(als[base + j] + ald_sh[d]) - m_sh[d]);
        }
        __syncthreads();

        const int c4 = t & 31, rs = t >> 5;
        float4 acc[8];
#pragma unroll
        for (int d = 0; d < 8; d++) acc[d] = make_float4(0.f, 0.f, 0.f, 0.f);
        const float4* h4 = reinterpret_cast<const float4*>(h) + (size_t)base * 32 + c4;
        const float* wrow = sbig + rs * 64 * 8;
#pragma unroll 4
        for (int jj = 0; jj < 64; jj++) {
            float4 hv = h4[(size_t)(rs * 64 + jj) * 32];
            const float* wj = wrow + jj * 8;
#pragma unroll
            for (int d = 0; d < 8; d++) fma4(acc[d], wj[d], hv);
        }
        __syncthreads();
        // stage per-slice partials, tree-reduce, one atomic per output
        float4* st4 = reinterpret_cast<float4*>(sbig) + rs * 256;
#pragma unroll
        for (int d = 0; d < 8; d++) st4[d * 32 + c4] = acc[d];
        __syncthreads();
        float s0 = 0.f, s1 = 0.f, s2 = 0.f, s3 = 0.f;
#pragma unroll
        for (int rr = 0; rr < 8; rr++) {
            float4 v = reinterpret_cast<const float4*>(sbig)[rr * 256 + t];
            s0 += v.x; s1 += v.y; s2 += v.z; s3 += v.w;
        }
        const int d = t >> 5, c = (t & 31) * 4;
        float* yo = y + (size_t)(d0 + d) * DDIM + c;
        atomicAdd(yo + 0, s0); atomicAdd(yo + 1, s1);
        atomicAdd(yo + 2, s2); atomicAdd(yo + 3, s3);
    } else {
        // -------- AG dsts: warp handles 4 dsts; 32-row h_ab tile in smem --------
        const int ablk = blockIdx.x - 128;
        const int b = ablk >> 6, chunk = ablk & 63;
        float* als_sh = ssmall;
        {
            const float4* hsrc = reinterpret_cast<const float4*>(h + (size_t)b * 32 * DDIM);
            float4* hd = reinterpret_cast<float4*>(sbig);
#pragma unroll
            for (int i = 0; i < 4; i++) hd[t + 256 * i] = hsrc[t + 256 * i];
            if (t < 32) als_sh[t] = als[b * 32 + t];
        }
        __syncthreads();
        const int w = t >> 5, l = t & 31;
        const int j0 = NAB + b * GSZ + chunk * 32 + w * 4;

        float e[4], es[4], wv[4], inv[4], wself[4];
#pragma unroll
        for (int d = 0; d < 4; d++) {
            float aldv = ald[j0 + d];
            e[d] = lrelu(als_sh[l] + aldv);
            es[d] = lrelu(als[j0 + d] + aldv);
        }
#pragma unroll
        for (int d = 0; d < 4; d++) {
            float m = e[d];
#pragma unroll
            for (int off = 16; off; off >>= 1) m = fmaxf(m, __shfl_xor_sync(0xffffffffu, m, off));
            m = fmaxf(m, es[d]);
            wv[d] = __expf(e[d] - m);
            float s = wv[d];
#pragma unroll
            for (int off = 16; off; off >>= 1) s += __shfl_xor_sync(0xffffffffu, s, off);
            wself[d] = __expf(es[d] - m);
            inv[d] = 1.f / (s + wself[d] + 1e-16f);
        }
        swT[w][l] = make_float4(wv[0], wv[1], wv[2], wv[3]);
        __syncwarp();

        float4 acc[4];
#pragma unroll
        for (int d = 0; d < 4; d++) {
            float4 hs = reinterpret_cast<const float4*>(h + (size_t)(j0 + d) * DDIM)[l];
            acc[d] = make_float4(wself[d] * hs.x, wself[d] * hs.y, wself[d] * hs.z, wself[d] * hs.w);
        }
        const float4* hab4 = reinterpret_cast<const float4*>(sbig);
#pragma unroll 8
        for (int l2 = 0; l2 < 32; l2++) {
            float4 wq = swT[w][l2];
            float4 hv = hab4[l2 * 32 + l];
            fma4(acc[0], wq.x, hv);
            fma4(acc[1], wq.y, hv);
            fma4(acc[2], wq.z, hv);
            fma4(acc[3], wq.w, hv);
        }
        float4 b4 = reinterpret_cast<const float4*>(bias)[l];
#pragma unroll
        for (int d = 0; d < 4; d++) {
            float4 r;
            r.x = acc[d].x * inv[d] + b4.x;
            r.y = acc[d].y * inv[d] + b4.y;
            r.z = acc[d].z * inv[d] + b4.z;
            r.w = acc[d].w * inv[d] + b4.w;
            if (do_relu) {
                r.x = fmaxf(r.x, 0.f); r.y = fmaxf(r.y, 0.f);
                r.z = fmaxf(r.z, 0.f); r.w = fmaxf(r.w, 0.f);
            }
            reinterpret_cast<float4*>(y + (size_t)(j0 + d) * DDIM)[l] = r;
        }
    }
}

// ---------------- finalize AB rows ----------------
__global__ void k_fin_ab(float* __restrict__ y, const float* __restrict__ h,
                         const float* __restrict__ bias, int do_relu) {
    int idx = blockIdx.x * 256 + threadIdx.x;
    int i = idx >> 7, c = idx & 127;
    float v = (y[idx] + g_wself[i] * h[idx]) * g_inv[i] + bias[c];
    if (do_relu) v = fmaxf(v, 0.f);
    y[idx] = v;
}

// ---------------- BN stats: AB (single block) + zero AG accumulators ----------------
__global__ void k_stats_ab(const float* __restrict__ gab, const float* __restrict__ bab) {
    int c = threadIdx.x;
    g_sum[c] = 0.f;
    g_ssq[c] = 0.f;
    const float* src = (c < 128) ? (g_z + c) : (g_x + c - 128);
    float s = 0.f, ss = 0.f;
    for (int r = 0; r < NAB; r++) {
        float v = src[(size_t)r * DDIM];
        s += v; ss += v * v;
    }
    float mean = s * (1.f / NAB);
    float var = ss * (1.f / NAB) - mean * mean;
    float sc = gab[c] * rsqrtf(var + 1e-5f);
    g_scA[c] = sc;
    g_shA[c] = bab[c] - mean * sc;
}

// ---------------- BN stats: AG partial sums (atomic) ----------------
__global__ void k_stats_ag() {
    int c = threadIdx.x;
    int r0 = NAB + blockIdx.x * 64;
    const float* src = (c < 128) ? (g_z + (size_t)r0 * DDIM + c)
                                 : (g_x + (size_t)r0 * DDIM + c - 128);
    float s = 0.f, ss = 0.f;
    for (int r = 0; r < 64; r++) {
        float v = src[(size_t)r * DDIM];
        s += v; ss += v * v;
    }
    atomicAdd(&g_sum[c], s);
    atomicAdd(&g_ssq[c], ss);
}

__device__ __forceinline__ void bnss(float s, float q, float g, float b, float invn,
                                     float& sc, float& sh) {
    float mean = s * invn;
    float var = q * invn - mean * mean;
    sc = g * rsqrtf(var + 1e-5f);
    sh = b - mean * sc;
}

// ---------------- fused BN -> ReLU -> FC epilogue, warp per row ----------------
__global__ void k_apply(float* __restrict__ out,
                        const float* __restrict__ fcw, const float* __restrict__ fcb,
                        const float* __restrict__ agw, const float* __restrict__ agb,
                        const float* __restrict__ gag, const float* __restrict__ bag) {
    const int row = blockIdx.x * 8 + (threadIdx.x >> 5);
    const int l = threadIdx.x & 31;
    float4 v1 = reinterpret_cast<const float4*>(g_z + (size_t)row * DDIM)[l];
    float4 v2 = reinterpret_cast<const float4*>(g_x + (size_t)row * DDIM)[l];
    float4 scA, shAv, scB, shB;
    const float* w;
    float fb;
    if (row < NAB) {
        scA = reinterpret_cast<const float4*>(g_scA)[l];
        shAv = reinterpret_cast<const float4*>(g_shA)[l];
        scB = reinterpret_cast<const float4*>(g_scA)[32 + l];
        shB = reinterpret_cast<const float4*>(g_shA)[32 + l];
        w = fcw; fb = fcb[0];
    } else {
        const float invn = 1.f / (float)NAGN;
        float4 s1 = reinterpret_cast<const float4*>(g_sum)[l];
        float4 q1 = reinterpret_cast<const float4*>(g_ssq)[l];
        float4 s2 = reinterpret_cast<const float4*>(g_sum)[32 + l];
        float4 q2 = reinterpret_cast<const float4*>(g_ssq)[32 + l];
        float4 gA = reinterpret_cast<const float4*>(gag)[l];
        float4 bA = reinterpret_cast<const float4*>(bag)[l];
        float4 gB = reinterpret_cast<const float4*>(gag)[32 + l];
        float4 bB = reinterpret_cast<const float4*>(bag)[32 + l];
        bnss(s1.x, q1.x, gA.x, bA.x, invn, scA.x, shAv.x);
        bnss(s1.y, q1.y, gA.y, bA.y, invn, scA.y, shAv.y);
        bnss(s1.z, q1.z, gA.z, bA.z, invn, scA.z, shAv.z);
        bnss(s1.w, q1.w, gA.w, bA.w, invn, scA.w, shAv.w);
        bnss(s2.x, q2.x, gB.x, bB.x, invn, scB.x, shB.x);
        bnss(s2.y, q2.y, gB.y, bB.y, invn, scB.y, shB.y);
        bnss(s2.z, q2.z, gB.z, bB.z, invn, scB.z, shB.z);
        bnss(s2.w, q2.w, gB.w, bB.w, invn, scB.w, shB.w);
        w = agw; fb = agb[0];
    }
    float4 w1 = reinterpret_cast<const float4*>(w)[l];
    float4 w2 = reinterpret_cast<const float4*>(w)[32 + l];
    float sum = 0.f;
    sum += fmaxf(v1.x * scA.x + shAv.x, 0.f) * w1.x;
    sum += fmaxf(v1.y * scA.y + shAv.y, 0.f) * w1.y;
    sum += fmaxf(v1.z * scA.z + shAv.z, 0.f) * w1.z;
    sum += fmaxf(v1.w * scA.w + shAv.w, 0.f) * w1.w;
    sum += fmaxf(v2.x * scB.x + shB.x, 0.f) * w2.x;
    sum += fmaxf(v2.y * scB.y + shB.y, 0.f) * w2.y;
    sum += fmaxf(v2.z * scB.z + shB.z, 0.f) * w2.z;
    sum += fmaxf(v2.w * scB.w + shB.w, 0.f) * w2.w;
#pragma unroll
    for (int off = 16; off; off >>= 1) sum += __shfl_xor_sync(0xffffffffu, sum, off);
    if (l == 0) out[row] = sum + fb;
}

// ---------------- host ----------------
extern "C" void kernel_launch(void* const* d_in, const int* in_sizes, int n_in,
                              void* d_out, int out_size) {
    const float* ab  = (const float*)d_in[0];
    const float* ag  = (const float*)d_in[1];
    const float* W1  = (const float*)d_in[2];
    const float* as1 = (const float*)d_in[3];
    const float* ad1 = (const float*)d_in[4];
    const float* b1  = (const float*)d_in[5];
    const float* W2  = (const float*)d_in[6];
    const float* as2 = (const float*)d_in[7];
    const float* ad2 = (const float*)d_in[8];
    const float* b2  = (const float*)d_in[9];
    const float* gab = (const float*)d_in[10];
    const float* bab = (const float*)d_in[11];
    const float* gag = (const float*)d_in[12];
    const float* bag = (const float*)d_in[13];
    const float* fcw = (const float*)d_in[14];
    const float* fcb = (const float*)d_in[15];
    const float* agw = (const float*)d_in[16];
    const float* agb = (const float*)d_in[17];
    float* out = (float*)d_out;

    float *px, *ph, *py, *pz, *pals, *pald;
    cudaGetSymbolAddress((void**)&px, g_x);
    cudaGetSymbolAddress((void**)&ph, g_h);
    cudaGetSymbolAddress((void**)&py, g_y);
    cudaGetSymbolAddress((void**)&pz, g_z);
    cudaGetSymbolAddress((void**)&pals, g_als);
    cudaGetSymbolAddress((void**)&pald, g_ald);

    const int SMEM_GEMM = (16384 + 8192) * 4;   // 96 KB
    cudaFuncSetAttribute(k_gemm, cudaFuncAttributeMaxDynamicSharedMemorySize, SMEM_GEMM);

    k_concat<<<256, 256>>>((const float4*)ab, (const float4*)ag);

    // ---- layer 1 ----
    k_gemm<<<260, 256, SMEM_GEMM>>>(px, W1, as1, ad1, ph, pals, pald);
    k_softmax_ab<<<256, 256>>>(pals, pald, py);
    k_agg<<<640, 256>>>(ph, pals, pald, b1, py, 1);
    k_fin_ab<<<128, 256>>>(py, ph, b1, 1);

    // ---- layer 2 ----
    k_gemm<<<260, 256, SMEM_GEMM>>>(py, W2, as2, ad2, ph, pals, pald);
    k_softmax_ab<<<256, 256>>>(pals, pald, pz);
    k_agg<<<640, 256>>>(ph, pals, pald, b2, pz, 0);
    k_fin_ab<<<128, 256>>>(pz, ph, b2, 0);

    // ---- BN + FC epilogue ----
    k_stats_ab<<<1, 256>>>(gab, bab);
    k_stats_ag<<<256, 256>>>();
    k_apply<<<2080, 256>>>(out, fcw, fcb, agw, agb, gag, bag);
}

// round 3
// speedup vs baseline: 1.5449x; 1.2647x over previous
#include <cuda_runtime.h>

#define NAB 256
#define NAGN 16384
#define NTOT 16640
#define DDIM 128
#define GSZ 2048

typedef unsigned long long ull;

// ---------------- scratch (device globals; no allocation) ----------------
__device__ float g_h[NTOT * DDIM];
__device__ float g_y[NTOT * DDIM];
__device__ float g_z[NTOT * DDIM];
__device__ float g_als[NTOT];
__device__ float g_ald[NTOT];
__device__ float g_zsum[NAB];
__device__ float g_sum[2 * DDIM];
__device__ float g_ssq[2 * DDIM];
__device__ float g_scA[2 * DDIM];
__device__ float g_shA[2 * DDIM];

__device__ __forceinline__ float lrelu(float e) { return e > 0.f ? e : 0.2f * e; }

// ---- packed f32x2 helpers (Blackwell FFMA2) ----
__device__ __forceinline__ ull dup2(float s) {
    ull d; unsigned u = __float_as_uint(s);
    asm("mov.b64 %0, {%1, %1};" : "=l"(d) : "r"(u));
    return d;
}
__device__ __forceinline__ void ffma2(ull& acc, ull a, ull b) {
    asm("fma.rn.f32x2 %0, %1, %2, %0;" : "+l"(acc) : "l"(a), "l"(b));
}
__device__ __forceinline__ void unpk(float& lo, float& hi, ull v) {
    unsigned a, b;
    asm("mov.b64 {%0, %1}, %2;" : "=r"(a), "=r"(b) : "l"(v));
    lo = __uint_as_float(a); hi = __uint_as_float(b);
}

// ---------------- GEMM: H = X @ W, plus al_src/al_dst row dots ----------------
// 260 blocks x 256 thr, 64 rows/block. FFMA2 inner: col-paired accumulators.
__global__ void __launch_bounds__(256, 2)
k_gemm(const float* __restrict__ X0, const float* __restrict__ X1,
       const float* __restrict__ W,
       const float* __restrict__ asrc, const float* __restrict__ adst,
       float* __restrict__ H, float* __restrict__ ALS, float* __restrict__ ALD,
       float* __restrict__ yz) {
    extern __shared__ float sm[];
    float* Ws = sm;                 // 128*128
    float* Xs = sm + 16384;         // 64*128
    const int t = threadIdx.x;
    const int row0 = blockIdx.x * 64;

    // zero the AB region of the aggregation target + zsum (blocks 0..3)
    if (row0 < NAB) {
        float4* z4 = reinterpret_cast<float4*>(yz) + row0 * 32;
#pragma unroll
        for (int i = 0; i < 8; i++) z4[t + 256 * i] = make_float4(0.f, 0.f, 0.f, 0.f);
        if (blockIdx.x == 0) g_zsum[t] = 0.f;
    }

    const float* X = (row0 < NAB) ? (X0 + (size_t)row0 * DDIM)
                                  : (X1 + (size_t)(row0 - NAB) * DDIM);

    const float4* W4 = reinterpret_cast<const float4*>(W);
    float4* Ws4s = reinterpret_cast<float4*>(Ws);
#pragma unroll
    for (int i = 0; i < 16; i++) Ws4s[t + 256 * i] = W4[t + 256 * i];
    const float4* Xg4 = reinterpret_cast<const float4*>(X);
    float4* Xs4s = reinterpret_cast<float4*>(Xs);
#pragma unroll
    for (int i = 0; i < 8; i++) Xs4s[t + 256 * i] = Xg4[t + 256 * i];
    __syncthreads();

    const int col4 = t & 31;
    const int rg = t >> 5;
    ull a0[8], a1[8];
#pragma unroll
    for (int r = 0; r < 8; r++) { a0[r] = 0ull; a1[r] = 0ull; }

    const ulonglong2* Wsu = reinterpret_cast<const ulonglong2*>(Ws);
    const float4* Xs4 = reinterpret_cast<const float4*>(Xs);

#pragma unroll 2
    for (int k0 = 0; k0 < DDIM; k0 += 4) {
        ulonglong2 w0 = Wsu[(k0 + 0) * 32 + col4];
        ulonglong2 w1 = Wsu[(k0 + 1) * 32 + col4];
        ulonglong2 w2 = Wsu[(k0 + 2) * 32 + col4];
        ulonglong2 w3 = Wsu[(k0 + 3) * 32 + col4];
#pragma unroll
        for (int r = 0; r < 8; r++) {
            float4 xr = Xs4[(rg * 8 + r) * 32 + (k0 >> 2)];
            ull xd;
            xd = dup2(xr.x); ffma2(a0[r], xd, w0.x); ffma2(a1[r], xd, w0.y);
            xd = dup2(xr.y); ffma2(a0[r], xd, w1.x); ffma2(a1[r], xd, w1.y);
            xd = dup2(xr.z); ffma2(a0[r], xd, w2.x); ffma2(a1[r], xd, w2.y);
            xd = dup2(xr.w); ffma2(a0[r], xd, w3.x); ffma2(a1[r], xd, w3.y);
        }
    }

    float4* H4 = reinterpret_cast<float4*>(H + (size_t)row0 * DDIM);
    float4 as4 = reinterpret_cast<const float4*>(asrc)[col4];
    float4 ad4 = reinterpret_cast<const float4*>(adst)[col4];
#pragma unroll
    for (int r = 0; r < 8; r++) {
        float4 v;
        unpk(v.x, v.y, a0[r]);
        unpk(v.z, v.w, a1[r]);
        H4[(rg * 8 + r) * 32 + col4] = v;
        float ps = v.x * as4.x + v.y * as4.y + v.z * as4.z + v.w * as4.w;
        float pd = v.x * ad4.x + v.y * ad4.y + v.z * ad4.z + v.w * ad4.w;
#pragma unroll
        for (int off = 16; off; off >>= 1) {
            ps += __shfl_xor_sync(0xffffffffu, ps, off);
            pd += __shfl_xor_sync(0xffffffffu, pd, off);
        }
        if (col4 == 0) {
            ALS[row0 + rg * 8 + r] = ps;
            ALD[row0 + rg * 8 + r] = pd;
        }
    }
}

// ---------------- fused aggregation + softmax (no max-shift) ----------------
// blocks 0..255: AB dsts (batch, 256-src chunk, dst-octet), partial sums + z via atomics
// blocks 256..767: AG dsts, fully fused softmax + weighted sum
__global__ void __launch_bounds__(256, 3)
k_agg(const float* __restrict__ h, const float* __restrict__ als,
      const float* __restrict__ ald, const float* __restrict__ bias,
      float* __restrict__ y, int do_relu) {
    __shared__ __align__(16) float sbig[8192];  // AB: w[256][8] then staging | AG: h_ab 32x128
    __shared__ float4 swT[8][32];
    __shared__ float ssmall[16];
    const int t = threadIdx.x;

    if (blockIdx.x < 256) {
        // -------- AB dsts --------
        const int blk = blockIdx.x;
        const int b = blk >> 5, q = (blk >> 2) & 7, dq = blk & 3;
        const int base = NAB + b * GSZ + q * 256;
        const int d0 = b * 32 + dq * 8;
        float* ald_sh = ssmall;
        float* szs = ssmall + 8;
        if (t < 8) { ald_sh[t] = ald[d0 + t]; szs[t] = 0.f; }
        __syncthreads();
        // fill exp weights [256 src][8 dst] + accumulate z per dst
        {
            const int dme = t & 7;
            const float aldme = ald_sh[dme];
            float zloc = 0.f;
#pragma unroll
            for (int i = 0; i < 8; i++) {
                int idx = t + 256 * i;
                int j = idx >> 3;
                float e = __expf(lrelu(als[base + j] + aldme));
                sbig[idx] = e;
                zloc += e;
            }
            atomicAdd(&szs[dme], zloc);
        }
        __syncthreads();
        if (t < 8) atomicAdd(&g_zsum[d0 + t], szs[t]);

        const int c4 = t & 31, rs = t >> 5;
        ull acc2[4][4];  // [dst-pair][col]
#pragma unroll
        for (int dp = 0; dp < 4; dp++)
#pragma unroll
            for (int c = 0; c < 4; c++) acc2[dp][c] = 0ull;

        const float4* h4 = reinterpret_cast<const float4*>(h) + (size_t)base * 32 + c4;
        const ull* w8 = reinterpret_cast<const ull*>(sbig);
#pragma unroll 4
        for (int jj = 0; jj < 32; jj++) {
            const int j = rs * 32 + jj;
            float4 hv = h4[(size_t)j * 32];
            ull hd0 = dup2(hv.x), hd1 = dup2(hv.y), hd2 = dup2(hv.z), hd3 = dup2(hv.w);
#pragma unroll
            for (int dp = 0; dp < 4; dp++) {
                ull a = w8[j * 4 + dp];
                ffma2(acc2[dp][0], a, hd0); ffma2(acc2[dp][1], a, hd1);
                ffma2(acc2[dp][2], a, hd2); ffma2(acc2[dp][3], a, hd3);
            }
        }
        __syncthreads();
        // stage per-slice partials [8rs][8d][32 f4], tree-reduce, one atomic per out
        float4* st4 = reinterpret_cast<float4*>(sbig) + rs * 256;
#pragma unroll
        for (int dp = 0; dp < 4; dp++) {
            float4 ve, vo;
            unpk(ve.x, vo.x, acc2[dp][0]);
            unpk(ve.y, vo.y, acc2[dp][1]);
            unpk(ve.z, vo.z, acc2[dp][2]);
            unpk(ve.w, vo.w, acc2[dp][3]);
            st4[(2 * dp) * 32 + c4] = ve;
            st4[(2 * dp + 1) * 32 + c4] = vo;
        }
        __syncthreads();
        float s0 = 0.f, s1 = 0.f, s2 = 0.f, s3 = 0.f;
#pragma unroll
        for (int rr = 0; rr < 8; rr++) {
            float4 v = reinterpret_cast<const float4*>(sbig)[rr * 256 + t];
            s0 += v.x; s1 += v.y; s2 += v.z; s3 += v.w;
        }
        const int d = t >> 5, c = (t & 31) * 4;
        float* yo = y + (size_t)(d0 + d) * DDIM + c;
        atomicAdd(yo + 0, s0); atomicAdd(yo + 1, s1);
        atomicAdd(yo + 2, s2); atomicAdd(yo + 3, s3);
    } else {
        // -------- AG dsts: warp handles 4 dsts; 32-row h_ab tile in smem --------
        const int ablk = blockIdx.x - 256;
        const int b = ablk >> 6, chunk = ablk & 63;
        {
            const float4* hsrc = reinterpret_cast<const float4*>(h + (size_t)b * 32 * DDIM);
            float4* hd = reinterpret_cast<float4*>(sbig);
#pragma unroll
            for (int i = 0; i < 4; i++) hd[t + 256 * i] = hsrc[t + 256 * i];
            if (t < 16) ssmall[t] = 0.f;
        }
        __shared__ float als_sh[32];
        if (t < 32) als_sh[t] = als[b * 32 + t];
        __syncthreads();
        const int w = t >> 5, l = t & 31;
        const int j0 = NAB + b * GSZ + chunk * 32 + w * 4;

        float wv[4], inv[4], wself[4];
#pragma unroll
        for (int d = 0; d < 4; d++) {
            float aldv = ald[j0 + d];
            wv[d] = __expf(lrelu(als_sh[l] + aldv));
            wself[d] = __expf(lrelu(als[j0 + d] + aldv));
            float s = wv[d];
#pragma unroll
            for (int off = 16; off; off >>= 1) s += __shfl_xor_sync(0xffffffffu, s, off);
            inv[d] = 1.f / (s + wself[d] + 1e-16f);
        }
        swT[w][l] = make_float4(wv[0], wv[1], wv[2], wv[3]);
        __syncwarp();

        ull acc01[4], acc23[4];   // (d0,d1) and (d2,d3) per col
#pragma unroll
        for (int c = 0; c < 4; c++) { acc01[c] = 0ull; acc23[c] = 0ull; }

        const float4* hab4 = reinterpret_cast<const float4*>(sbig);
        const ulonglong2* swu = reinterpret_cast<const ulonglong2*>(&swT[w][0]);
#pragma unroll 8
        for (int l2 = 0; l2 < 32; l2++) {
            ulonglong2 wq = swu[l2];
            float4 hv = hab4[l2 * 32 + l];
            ull hd;
            hd = dup2(hv.x); ffma2(acc01[0], wq.x, hd); ffma2(acc23[0], wq.y, hd);
            hd = dup2(hv.y); ffma2(acc01[1], wq.x, hd); ffma2(acc23[1], wq.y, hd);
            hd = dup2(hv.z); ffma2(acc01[2], wq.x, hd); ffma2(acc23[2], wq.y, hd);
            hd = dup2(hv.w); ffma2(acc01[3], wq.x, hd); ffma2(acc23[3], wq.y, hd);
        }
        float sd[4][4];
#pragma unroll
        for (int c = 0; c < 4; c++) {
            unpk(sd[0][c], sd[1][c], acc01[c]);
            unpk(sd[2][c], sd[3][c], acc23[c]);
        }
        float4 b4 = reinterpret_cast<const float4*>(bias)[l];
#pragma unroll
        for (int d = 0; d < 4; d++) {
            float4 hs = reinterpret_cast<const float4*>(h + (size_t)(j0 + d) * DDIM)[l];
            float4 r;
            r.x = (sd[d][0] + wself[d] * hs.x) * inv[d] + b4.x;
            r.y = (sd[d][1] + wself[d] * hs.y) * inv[d] + b4.y;
            r.z = (sd[d][2] + wself[d] * hs.z) * inv[d] + b4.z;
            r.w = (sd[d][3] + wself[d] * hs.w) * inv[d] + b4.w;
            if (do_relu) {
                r.x = fmaxf(r.x, 0.f); r.y = fmaxf(r.y, 0.f);
                r.z = fmaxf(r.z, 0.f); r.w = fmaxf(r.w, 0.f);
            }
            reinterpret_cast<float4*>(y + (size_t)(j0 + d) * DDIM)[l] = r;
        }
    }
}

// ---------------- finalize AB rows: add self, normalize, bias (+relu) ----------------
__global__ void k_fin_ab(float* __restrict__ y, const float* __restrict__ h,
                         const float* __restrict__ als, const float* __restrict__ ald,
                         const float* __restrict__ bias, int do_relu) {
    int idx = blockIdx.x * 256 + threadIdx.x;
    int i = idx >> 7, c = idx & 127;
    float es = __expf(lrelu(als[i] + ald[i]));
    float v = (y[idx] + es * h[idx]) / (g_zsum[i] + es + 1e-16f) + bias[c];
    if (do_relu) v = fmaxf(v, 0.f);
    y[idx] = v;
}

// ---------------- BN stats: AB (single block) + zero AG accumulators ----------------
__global__ void k_stats_ab(const float* __restrict__ gab, const float* __restrict__ bab,
                           const float* __restrict__ ab) {
    int c = threadIdx.x;
    g_sum[c] = 0.f;
    g_ssq[c] = 0.f;
    const float* src = (c < 128) ? (g_z + c) : (ab + c - 128);
    float s = 0.f, ss = 0.f;
    for (int r = 0; r < NAB; r++) {
        float v = src[(size_t)r * DDIM];
        s += v; ss += v * v;
    }
    float mean = s * (1.f / NAB);
    float var = ss * (1.f / NAB) - mean * mean;
    float sc = gab[c] * rsqrtf(var + 1e-5f);
    g_scA[c] = sc;
    g_shA[c] = bab[c] - mean * sc;
}

// ---------------- BN stats: AG partial sums (atomic) ----------------
__global__ void k_stats_ag(const float* __restrict__ ag) {
    int c = threadIdx.x;
    int r0 = blockIdx.x * 64;   // AG-local row
    const float* src = (c < 128) ? (g_z + (size_t)(NAB + r0) * DDIM + c)
                                 : (ag + (size_t)r0 * DDIM + c - 128);
    float s = 0.f, ss = 0.f;
    for (int r = 0; r < 64; r++) {
        float v = src[(size_t)r * DDIM];
        s += v; ss += v * v;
    }
    atomicAdd(&g_sum[c], s);
    atomicAdd(&g_ssq[c], ss);
}

__device__ __forceinline__ void bnss(float s, float q, float g, float b, float invn,
                                     float& sc, float& sh) {
    float mean = s * invn;
    float var = q * invn - mean * mean;
    sc = g * rsqrtf(var + 1e-5f);
    sh = b - mean * sc;
}

// ---------------- fused BN -> ReLU -> FC epilogue, warp per row ----------------
__global__ void k_apply(float* __restrict__ out,
                        const float* __restrict__ ab, const float* __restrict__ ag,
                        const float* __restrict__ fcw, const float* __restrict__ fcb,
                        const float* __restrict__ agw, const float* __restrict__ agb,
                        const float* __restrict__ gag, const float* __restrict__ bag) {
    const int row = blockIdx.x * 8 + (threadIdx.x >> 5);
    const int l = threadIdx.x & 31;
    float4 v1 = reinterpret_cast<const float4*>(g_z + (size_t)row * DDIM)[l];
    float4 v2 = (row < NAB)
        ? reinterpret_cast<const float4*>(ab + (size_t)row * DDIM)[l]
        : reinterpret_cast<const float4*>(ag + (size_t)(row - NAB) * DDIM)[l];
    float4 scA, shAv, scB, shB;
    const float* w;
    float fb;
    if (row < NAB) {
        scA = reinterpret_cast<const float4*>(g_scA)[l];
        shAv = reinterpret_cast<const float4*>(g_shA)[l];
        scB = reinterpret_cast<const float4*>(g_scA)[32 + l];
        shB = reinterpret_cast<const float4*>(g_shA)[32 + l];
        w = fcw; fb = fcb[0];
    } else {
        const float invn = 1.f / (float)NAGN;
        float4 s1 = reinterpret_cast<const float4*>(g_sum)[l];
        float4 q1 = reinterpret_cast<const float4*>(g_ssq)[l];
        float4 s2 = reinterpret_cast<const float4*>(g_sum)[32 + l];
        float4 q2 = reinterpret_cast<const float4*>(g_ssq)[32 + l];
        float4 gA = reinterpret_cast<const float4*>(gag)[l];
        float4 bA = reinterpret_cast<const float4*>(bag)[l];
        float4 gB = reinterpret_cast<const float4*>(gag)[32 + l];
        float4 bB = reinterpret_cast<const float4*>(bag)[32 + l];
        bnss(s1.x, q1.x, gA.x, bA.x, invn, scA.x, shAv.x);
        bnss(s1.y, q1.y, gA.y, bA.y, invn, scA.y, shAv.y);
        bnss(s1.z, q1.z, gA.z, bA.z, invn, scA.z, shAv.z);
        bnss(s1.w, q1.w, gA.w, bA.w, invn, scA.w, shAv.w);
        bnss(s2.x, q2.x, gB.x, bB.x, invn, scB.x, shB.x);
        bnss(s2.y, q2.y, gB.y, bB.y, invn, scB.y, shB.y);
        bnss(s2.z, q2.z, gB.z, bB.z, invn, scB.z, shB.z);
        bnss(s2.w, q2.w, gB.w, bB.w, invn, scB.w, shB.w);
        w = agw; fb = agb[0];
    }
    float4 w1 = reinterpret_cast<const float4*>(w)[l];
    float4 w2 = reinterpret_cast<const float4*>(w)[32 + l];
    float sum = 0.f;
    sum += fmaxf(v1.x * scA.x + shAv.x, 0.f) * w1.x;
    sum += fmaxf(v1.y * scA.y + shAv.y, 0.f) * w1.y;
    sum += fmaxf(v1.z * scA.z + shAv.z, 0.f) * w1.z;
    sum += fmaxf(v1.w * scA.w + shAv.w, 0.f) * w1.w;
    sum += fmaxf(v2.x * scB.x + shB.x, 0.f) * w2.x;
    sum += fmaxf(v2.y * scB.y + shB.y, 0.f) * w2.y;
    sum += fmaxf(v2.z * scB.z + shB.z, 0.f) * w2.z;
    sum += fmaxf(v2.w * scB.w + shB.w, 0.f) * w2.w;
#pragma unroll
    for (int off = 16; off; off >>= 1) sum += __shfl_xor_sync(0xffffffffu, sum, off);
    if (l == 0) out[row] = sum + fb;
}

// ---------------- host ----------------
extern "C" void kernel_launch(void* const* d_in, const int* in_sizes, int n_in,
                              void* d_out, int out_size) {
    const float* ab  = (const float*)d_in[0];
    const float* ag  = (const float*)d_in[1];
    const float* W1  = (const float*)d_in[2];
    const float* as1 = (const float*)d_in[3];
    const float* ad1 = (const float*)d_in[4];
    const float* b1  = (const float*)d_in[5];
    const float* W2  = (const float*)d_in[6];
    const float* as2 = (const float*)d_in[7];
    const float* ad2 = (const float*)d_in[8];
    const float* b2  = (const float*)d_in[9];
    const float* gab = (const float*)d_in[10];
    const float* bab = (const float*)d_in[11];
    const float* gag = (const float*)d_in[12];
    const float* bag = (const float*)d_in[13];
    const float* fcw = (const float*)d_in[14];
    const float* fcb = (const float*)d_in[15];
    const float* agw = (const float*)d_in[16];
    const float* agb = (const float*)d_in[17];
    float* out = (float*)d_out;

    float *ph, *py, *pz, *pals, *pald;
    cudaGetSymbolAddress((void**)&ph, g_h);
    cudaGetSymbolAddress((void**)&py, g_y);
    cudaGetSymbolAddress((void**)&pz, g_z);
    cudaGetSymbolAddress((void**)&pals, g_als);
    cudaGetSymbolAddress((void**)&pald, g_ald);

    const int SMEM_GEMM = (16384 + 8192) * 4;   // 96 KB
    cudaFuncSetAttribute(k_gemm, cudaFuncAttributeMaxDynamicSharedMemorySize, SMEM_GEMM);

    // ---- layer 1 ----
    k_gemm<<<260, 256, SMEM_GEMM>>>(ab, ag, W1, as1, ad1, ph, pals, pald, py);
    k_agg<<<768, 256>>>(ph, pals, pald, b1, py, 1);
    k_fin_ab<<<128, 256>>>(py, ph, pals, pald, b1, 1);

    // ---- layer 2 ----
    k_gemm<<<260, 256, SMEM_GEMM>>>(py, py + NAB * DDIM, W2, as2, ad2, ph, pals, pald, pz);
    k_agg<<<768, 256>>>(ph, pals, pald, b2, pz, 0);
    k_fin_ab<<<128, 256>>>(pz, ph, pals, pald, b2, 0);

    // ---- BN + FC epilogue ----
    k_stats_ab<<<1, 256>>>(gab, bab, ab);
    k_stats_ag<<<256, 256>>>(ag);
    k_apply<<<2080, 256>>>(out, ab, ag, fcw, fcb, agw, agb, gag, bag);
}